// round 11
// baseline (speedup 1.0000x reference)
#include <cuda_runtime.h>
#include <cstdint>

#define BATCH 2
#define SEQ   4096
#define DMODEL 512
#define NHEAD 8
#define HDIM  64

// Scratch (allocation-free rule: __device__ globals)
__device__ float g_Q[BATCH*SEQ*DMODEL];
__device__ float g_K[BATCH*SEQ*DMODEL];
__device__ float g_V[BATCH*SEQ*DMODEL];
__device__ float g_O[BATCH*SEQ*DMODEL];

__device__ __forceinline__ uint32_t cvt_tf32(float x) {
    uint32_t u; asm("cvt.rna.tf32.f32 %0, %1;" : "=r"(u) : "f"(x)); return u;
}
__device__ __forceinline__ void split_tf32(float x, uint32_t& hi, uint32_t& lo) {
    hi = cvt_tf32(x);
    lo = cvt_tf32(x - __uint_as_float(hi));
}
// m16n8k8 tf32 mma, fp32 accumulate
__device__ __forceinline__ void mma_tf32(float* c, const uint32_t* a, const uint32_t* b) {
    asm volatile(
        "mma.sync.aligned.m16n8k8.row.col.f32.tf32.tf32.f32 "
        "{%0,%1,%2,%3}, {%4,%5,%6,%7}, {%8,%9}, {%0,%1,%2,%3};\n"
        : "+f"(c[0]), "+f"(c[1]), "+f"(c[2]), "+f"(c[3])
        : "r"(a[0]), "r"(a[1]), "r"(a[2]), "r"(a[3]), "r"(b[0]), "r"(b[1]));
}

// ---------------------------------------------------------------------------
// Shared GEMM body: C[128,128 tile] = A @ W * scale (3x-tf32).
// Block 128x128, 8 warps (2m x 4n), warp tile 64x32.
// A and B tiles are pre-split into tf32 hi/lo at load time (bit-exact with
// in-loop splitting; kills the 4x/2x per-warp redundant split ALU).
// ---------------------------------------------------------------------------
__device__ __forceinline__ void gemm512_body(
    const float* __restrict__ A, const float* __restrict__ W,
    float* __restrict__ C, float scale, int m0, int n0)
{
    extern __shared__ float gsm[];
    float* Ahi = gsm;                 // 128 x 36 (+4 pad: conflict-free frag LDS)
    float* Alo = Ahi + 128*36;        // 128 x 36
    float* Bhi = Alo + 128*36;        // 32 x 132
    float* Blo = Bhi + 32*132;        // 32 x 132

    const int tid  = threadIdx.x;
    const int lane = tid & 31, warp = tid >> 5;
    const int wm = warp & 1, wn = warp >> 1;
    const int g = lane >> 2, t = lane & 3;

    float acc[4][4][4];
    #pragma unroll
    for (int i = 0; i < 4; i++)
        #pragma unroll
        for (int j = 0; j < 4; j++)
            #pragma unroll
            for (int k = 0; k < 4; k++) acc[i][j][k] = 0.f;

    for (int k0 = 0; k0 < 512; k0 += 32) {
        #pragma unroll
        for (int p = 0; p < 4; p++) {
            int lin = p*1024 + tid*4;
            int r = lin >> 5, c = lin & 31;
            float4 a = *(const float4*)&A[(size_t)(m0 + r)*512 + k0 + c];
            uint32_t h0,l0,h1,l1,h2,l2,h3,l3;
            split_tf32(a.x, h0, l0); split_tf32(a.y, h1, l1);
            split_tf32(a.z, h2, l2); split_tf32(a.w, h3, l3);
            *(float4*)&Ahi[r*36 + c] = make_float4(
                __uint_as_float(h0), __uint_as_float(h1),
                __uint_as_float(h2), __uint_as_float(h3));
            *(float4*)&Alo[r*36 + c] = make_float4(
                __uint_as_float(l0), __uint_as_float(l1),
                __uint_as_float(l2), __uint_as_float(l3));
        }
        #pragma unroll
        for (int p = 0; p < 4; p++) {
            int lin = p*1024 + tid*4;
            int r = lin >> 7, c = lin & 127;
            float4 b = *(const float4*)&W[(size_t)(k0 + r)*512 + n0 + c];
            uint32_t h0,l0,h1,l1,h2,l2,h3,l3;
            split_tf32(b.x, h0, l0); split_tf32(b.y, h1, l1);
            split_tf32(b.z, h2, l2); split_tf32(b.w, h3, l3);
            *(float4*)&Bhi[r*132 + c] = make_float4(
                __uint_as_float(h0), __uint_as_float(h1),
                __uint_as_float(h2), __uint_as_float(h3));
            *(float4*)&Blo[r*132 + c] = make_float4(
                __uint_as_float(l0), __uint_as_float(l1),
                __uint_as_float(l2), __uint_as_float(l3));
        }
        __syncthreads();

        #pragma unroll
        for (int ks = 0; ks < 4; ks++) {
            uint32_t ah[4][4], al[4][4];
            #pragma unroll
            for (int mt = 0; mt < 4; mt++) {
                int r0 = wm*64 + mt*16 + g;
                int cc = ks*8 + t;
                ah[mt][0] = __float_as_uint(Ahi[r0*36 + cc]);
                ah[mt][1] = __float_as_uint(Ahi[(r0+8)*36 + cc]);
                ah[mt][2] = __float_as_uint(Ahi[r0*36 + cc + 4]);
                ah[mt][3] = __float_as_uint(Ahi[(r0+8)*36 + cc + 4]);
                al[mt][0] = __float_as_uint(Alo[r0*36 + cc]);
                al[mt][1] = __float_as_uint(Alo[(r0+8)*36 + cc]);
                al[mt][2] = __float_as_uint(Alo[r0*36 + cc + 4]);
                al[mt][3] = __float_as_uint(Alo[(r0+8)*36 + cc + 4]);
            }
            #pragma unroll
            for (int nt = 0; nt < 4; nt++) {
                int cn = wn*32 + nt*8 + g;
                uint32_t bh[2], bl[2];
                bh[0] = __float_as_uint(Bhi[(ks*8 + t)*132 + cn]);
                bh[1] = __float_as_uint(Bhi[(ks*8 + t + 4)*132 + cn]);
                bl[0] = __float_as_uint(Blo[(ks*8 + t)*132 + cn]);
                bl[1] = __float_as_uint(Blo[(ks*8 + t + 4)*132 + cn]);
                #pragma unroll
                for (int mt = 0; mt < 4; mt++) {
                    mma_tf32(acc[mt][nt], ah[mt], bh);
                    mma_tf32(acc[mt][nt], al[mt], bh);
                    mma_tf32(acc[mt][nt], ah[mt], bl);
                }
            }
        }
        __syncthreads();
    }

    #pragma unroll
    for (int mt = 0; mt < 4; mt++) {
        int r0 = m0 + wm*64 + mt*16 + g;
        #pragma unroll
        for (int nt = 0; nt < 4; nt++) {
            int cn = n0 + wn*32 + nt*8 + 2*t;
            *(float2*)&C[(size_t)r0*512 + cn] =
                make_float2(acc[mt][nt][0]*scale, acc[mt][nt][1]*scale);
            *(float2*)&C[(size_t)(r0+8)*512 + cn] =
                make_float2(acc[mt][nt][2]*scale, acc[mt][nt][3]*scale);
        }
    }
}

// Smem for GEMM kernels: 2*(128*36) + 2*(32*132) floats = 70656 bytes.
#define GEMM_SMEM ((2*128*36 + 2*32*132) * (int)sizeof(float))

// Fused Q/K/V projection: blockIdx.z selects {qa*Wq->Q, ma*Wk->K, ma*Wv->V}.
// One 768-CTA grid instead of three 256-CTA grids: single wave tail, shared
// L2 residency of `ma` across the K and V slices.
__global__ __launch_bounds__(256) void gemm_qkv_kernel(
    const float* __restrict__ qa, const float* __restrict__ ma,
    const float* __restrict__ Wq, const float* __restrict__ Wk,
    const float* __restrict__ Wv,
    float* __restrict__ Q, float* __restrict__ K, float* __restrict__ V)
{
    const int z = blockIdx.z;
    const float* A = (z == 0) ? qa : ma;
    const float* W = (z == 0) ? Wq : (z == 1) ? Wk : Wv;
    float*       C = (z == 0) ? Q  : (z == 1) ? K  : V;
    const float scale = (z == 0) ? 0.125f : 1.0f;   // hd^-0.5 = 1/8 on Q
    gemm512_body(A, W, C, scale, blockIdx.y * 128, blockIdx.x * 128);
}

// Plain single-GEMM wrapper (output projection).
__global__ __launch_bounds__(256) void gemm512_kernel(
    const float* __restrict__ A, const float* __restrict__ W,
    float* __restrict__ C, float scale)
{
    gemm512_body(A, W, C, scale, blockIdx.y * 128, blockIdx.x * 128);
}

// ---------------------------------------------------------------------------
// Flash attention with additive bias.
// CTA = (b,h, 128 q-rows). 8 warps each own a 16-row q band (softmax stays
// quad-local). QK^T in 3x-tf32 with K hi/lo PRE-SPLIT at load (kills the 8x
// redundant per-warp split); V stored tf32-converted at load.
// ---------------------------------------------------------------------------
__global__ __launch_bounds__(256, 1) void flash_kernel(const float* __restrict__ bias)
{
    extern __shared__ float smf[];
    float* Qs  = smf;                // 128 x 68  raw fp32 Q
    float* Khi = Qs  + 128*68;       // 128 x 68  tf32-hi bit patterns
    float* Klo = Khi + 128*68;       // 128 x 68  tf32-lo bit patterns
    float* Vs  = Klo + 128*68;       // 128 x 68  tf32-converted V
    float* Ps  = Vs  + 128*68;       // 128 x 132 per-warp private P bands

    const int tid  = threadIdx.x;
    const int lane = tid & 31, warp = tid >> 5;
    const int g = lane >> 2, t = lane & 3;
    const int bh = blockIdx.x;           // bh fastest -> 16 CTAs share bias tile in L2
    const int b = bh >> 3, h = bh & 7;
    const int qb = blockIdx.y;

    const size_t qkv_base = ((size_t)b*SEQ)*DMODEL + h*HDIM;
    const float NEG = -1e30f;

    {   // load Q tile once (raw)
        const float* Qg = g_Q + qkv_base + (size_t)(qb*128)*DMODEL;
        #pragma unroll
        for (int p = 0; p < 8; p++) {
            int lin = p*1024 + tid*4;
            int r = lin >> 6, c = lin & 63;
            *(float4*)&Qs[r*68 + c] = *(const float4*)&Qg[(size_t)r*DMODEL + c];
        }
    }

    float oc[8][4];
    #pragma unroll
    for (int i = 0; i < 8; i++)
        #pragma unroll
        for (int j = 0; j < 4; j++) oc[i][j] = 0.f;
    float mr0 = NEG, mr1 = NEG, lr0 = 0.f, lr1 = 0.f;

    for (int kt = 0; kt < 32; kt++) {
        __syncthreads();   // all warps done with previous K/V tiles
        {
            const float* Kg = g_K + qkv_base + (size_t)(kt*128)*DMODEL;
            const float* Vg = g_V + qkv_base + (size_t)(kt*128)*DMODEL;
            #pragma unroll
            for (int p = 0; p < 8; p++) {
                int lin = p*1024 + tid*4;
                int r = lin >> 6, c = lin & 63;
                // K: split to hi/lo once for the whole CTA
                float4 kv = *(const float4*)&Kg[(size_t)r*DMODEL + c];
                uint32_t h0,l0,h1,l1,h2,l2,h3,l3;
                split_tf32(kv.x, h0, l0); split_tf32(kv.y, h1, l1);
                split_tf32(kv.z, h2, l2); split_tf32(kv.w, h3, l3);
                *(float4*)&Khi[r*68 + c] = make_float4(
                    __uint_as_float(h0), __uint_as_float(h1),
                    __uint_as_float(h2), __uint_as_float(h3));
                *(float4*)&Klo[r*68 + c] = make_float4(
                    __uint_as_float(l0), __uint_as_float(l1),
                    __uint_as_float(l2), __uint_as_float(l3));
                // V: store tf32-converted (conversion hoisted out of PV loop)
                float4 vv = *(const float4*)&Vg[(size_t)r*DMODEL + c];
                *(float4*)&Vs[r*68 + c] = make_float4(
                    __uint_as_float(cvt_tf32(vv.x)), __uint_as_float(cvt_tf32(vv.y)),
                    __uint_as_float(cvt_tf32(vv.z)), __uint_as_float(cvt_tf32(vv.w)));
            }
        }
        __syncthreads();

        // ---- S = Q @ K^T (3x tf32), warp tile 16 x 128 ----
        float sc[16][4];
        #pragma unroll
        for (int i = 0; i < 16; i++)
            #pragma unroll
            for (int j = 0; j < 4; j++) sc[i][j] = 0.f;

        #pragma unroll
        for (int ks = 0; ks < 8; ks++) {
            uint32_t ah[4], al[4];
            {
                int r0 = warp*16 + g;
                int cc = ks*8 + t;
                split_tf32(Qs[r0*68 + cc],         ah[0], al[0]);
                split_tf32(Qs[(r0+8)*68 + cc],     ah[1], al[1]);
                split_tf32(Qs[r0*68 + cc + 4],     ah[2], al[2]);
                split_tf32(Qs[(r0+8)*68 + cc + 4], ah[3], al[3]);
            }
            #pragma unroll
            for (int nt = 0; nt < 16; nt++) {
                int kr = (nt*8 + g)*68 + ks*8 + t;
                uint32_t bh2[2], bl2[2];
                bh2[0] = __float_as_uint(Khi[kr]);
                bh2[1] = __float_as_uint(Khi[kr + 4]);
                bl2[0] = __float_as_uint(Klo[kr]);
                bl2[1] = __float_as_uint(Klo[kr + 4]);
                mma_tf32(sc[nt], ah, bh2);
                mma_tf32(sc[nt], al, bh2);
                mma_tf32(sc[nt], ah, bl2);
            }
        }

        // ---- bias add + online softmax (fp32) ----
        const float* br0 = bias + (size_t)(qb*128 + warp*16 + g)*SEQ + kt*128 + 2*t;
        const float* br1 = br0 + (size_t)8*SEQ;
        float mx0 = NEG, mx1 = NEG;
        #pragma unroll
        for (int nt = 0; nt < 16; nt++) {
            float2 b0 = *(const float2*)(br0 + nt*8);
            float2 b1 = *(const float2*)(br1 + nt*8);
            sc[nt][0] += b0.x; sc[nt][1] += b0.y;
            sc[nt][2] += b1.x; sc[nt][3] += b1.y;
            mx0 = fmaxf(mx0, fmaxf(sc[nt][0], sc[nt][1]));
            mx1 = fmaxf(mx1, fmaxf(sc[nt][2], sc[nt][3]));
        }
        mx0 = fmaxf(mx0, __shfl_xor_sync(0xffffffffu, mx0, 1));
        mx0 = fmaxf(mx0, __shfl_xor_sync(0xffffffffu, mx0, 2));
        mx1 = fmaxf(mx1, __shfl_xor_sync(0xffffffffu, mx1, 1));
        mx1 = fmaxf(mx1, __shfl_xor_sync(0xffffffffu, mx1, 2));
        float nm0 = fmaxf(mr0, mx0), nm1 = fmaxf(mr1, mx1);
        float al0 = __expf(mr0 - nm0), al1 = __expf(mr1 - nm1);
        float s0 = 0.f, s1 = 0.f;
        #pragma unroll
        for (int nt = 0; nt < 16; nt++) {
            sc[nt][0] = __expf(sc[nt][0] - nm0);
            sc[nt][1] = __expf(sc[nt][1] - nm0);
            sc[nt][2] = __expf(sc[nt][2] - nm1);
            sc[nt][3] = __expf(sc[nt][3] - nm1);
            s0 += sc[nt][0] + sc[nt][1];
            s1 += sc[nt][2] + sc[nt][3];
        }
        s0 += __shfl_xor_sync(0xffffffffu, s0, 1);
        s0 += __shfl_xor_sync(0xffffffffu, s0, 2);
        s1 += __shfl_xor_sync(0xffffffffu, s1, 1);
        s1 += __shfl_xor_sync(0xffffffffu, s1, 2);
        lr0 = lr0*al0 + s0;  lr1 = lr1*al1 + s1;
        mr0 = nm0;           mr1 = nm1;
        #pragma unroll
        for (int nt = 0; nt < 8; nt++) {
            oc[nt][0] *= al0; oc[nt][1] *= al0;
            oc[nt][2] *= al1; oc[nt][3] *= al1;
        }

        // ---- stage P (tf32-converted) in warp-private smem band ----
        {
            int pr0 = (warp*16 + g)*132 + 2*t;
            int pr1 = pr0 + 8*132;
            #pragma unroll
            for (int nt = 0; nt < 16; nt++) {
                *(float2*)&Ps[pr0 + nt*8] = make_float2(
                    __uint_as_float(cvt_tf32(sc[nt][0])),
                    __uint_as_float(cvt_tf32(sc[nt][1])));
                *(float2*)&Ps[pr1 + nt*8] = make_float2(
                    __uint_as_float(cvt_tf32(sc[nt][2])),
                    __uint_as_float(cvt_tf32(sc[nt][3])));
            }
        }
        __syncwarp();

        // ---- O += P @ V (operands already tf32 in smem) ----
        #pragma unroll
        for (int ks = 0; ks < 16; ks++) {
            uint32_t pa[4];
            {
                int r0 = (warp*16 + g)*132;
                int cc = ks*8 + t;
                pa[0] = __float_as_uint(Ps[r0 + cc]);
                pa[1] = __float_as_uint(Ps[r0 + 8*132 + cc]);
                pa[2] = __float_as_uint(Ps[r0 + cc + 4]);
                pa[3] = __float_as_uint(Ps[r0 + 8*132 + cc + 4]);
            }
            #pragma unroll
            for (int nt = 0; nt < 8; nt++) {
                uint32_t vb[2];
                vb[0] = __float_as_uint(Vs[(ks*8 + t)*68 + nt*8 + g]);
                vb[1] = __float_as_uint(Vs[(ks*8 + t + 4)*68 + nt*8 + g]);
                mma_tf32(oc[nt], pa, vb);
            }
        }
    }

    // ---- epilogue: normalize and store ----
    float il0 = 1.f / lr0, il1 = 1.f / lr1;
    float* Og = g_O + qkv_base + (size_t)(qb*128)*DMODEL;
    int r0 = warp*16 + g;
    #pragma unroll
    for (int nt = 0; nt < 8; nt++) {
        int cn = nt*8 + 2*t;
        *(float2*)&Og[(size_t)r0*DMODEL + cn] =
            make_float2(oc[nt][0]*il0, oc[nt][1]*il0);
        *(float2*)&Og[(size_t)(r0+8)*DMODEL + cn] =
            make_float2(oc[nt][2]*il1, oc[nt][3]*il1);
    }
}

// ---------------------------------------------------------------------------
extern "C" void kernel_launch(void* const* d_in, const int* in_sizes, int n_in,
                              void* d_out, int out_size)
{
    const float* qa   = (const float*)d_in[0];
    const float* ma   = (const float*)d_in[1];
    const float* bias = (const float*)d_in[2];
    const float* Wq   = (const float*)d_in[3];
    const float* Wk   = (const float*)d_in[4];
    const float* Wv   = (const float*)d_in[5];
    const float* Wo   = (const float*)d_in[6];
    float* out = (float*)d_out;

    float *pQ, *pK, *pV, *pO;
    cudaGetSymbolAddress((void**)&pQ, g_Q);
    cudaGetSymbolAddress((void**)&pK, g_K);
    cudaGetSymbolAddress((void**)&pV, g_V);
    cudaGetSymbolAddress((void**)&pO, g_O);

    cudaFuncSetAttribute(gemm_qkv_kernel,
                         cudaFuncAttributeMaxDynamicSharedMemorySize, GEMM_SMEM);
    cudaFuncSetAttribute(gemm512_kernel,
                         cudaFuncAttributeMaxDynamicSharedMemorySize, GEMM_SMEM);

    // Fused Q/K/V projections: one 768-CTA grid (z selects which projection).
    gemm_qkv_kernel<<<dim3(4, 64, 3), 256, GEMM_SMEM>>>(qa, ma, Wq, Wk, Wv,
                                                        pQ, pK, pV);

    int smem_bytes = (4*128*68 + 128*132) * (int)sizeof(float);  // 206848
    cudaFuncSetAttribute(flash_kernel, cudaFuncAttributeMaxDynamicSharedMemorySize,
                         smem_bytes);
    flash_kernel<<<dim3(16, 32), 256, smem_bytes>>>(bias);

    gemm512_kernel<<<dim3(4, 64), 256, GEMM_SMEM>>>(pO, Wo, out, 1.0f);
}